// round 4
// baseline (speedup 1.0000x reference)
#include <cuda_runtime.h>
#include <cuda_bf16.h>
#include <cstdint>

// Problem constants (fixed shapes)
#define BATCH   128
#define SEQLEN  16384
#define NBANDS  20
#define TAPS    513
#define PAD     512                 // padlen = TAPS-1
#define EXTLEN  (SEQLEN + 2*PAD)    // 17408

// Tile config for main conv kernel
#define THREADS 256
#define POS     8                   // outputs per thread (4 packed f32x2 accs)
#define TI      (THREADS*POS)       // 2048 outputs per CTA
#define WIN     (TI + 2*PAD)        // 3072 window floats
#define SHSZ    (WIN + 32)          // tail pad for pipelined float4/ull2 overrun
#define CDUPSZ  1032                // >= U_max/ (ull elements), U_max = 1028

// Scratch (static device globals; no runtime allocation)
__device__ float g_ext[BATCH * EXTLEN];     // odd-extended signals
__device__ float g_c[NBANDS * TAPS];        // per-band autocorrelation c[m]
__device__ int   g_M[NBANDS];               // per-band half length M

// ---------------------------------------------------------------------------
// packed f32x2 FMA (FFMA2) — only reachable via PTX on sm_103a
// ---------------------------------------------------------------------------
__device__ __forceinline__ void ffma2(unsigned long long& acc,
                                      unsigned long long c,
                                      unsigned long long w) {
    asm("fma.rn.f32x2 %0, %1, %2, %0;" : "+l"(acc) : "l"(c), "l"(w));
}

// ---------------------------------------------------------------------------
// Kernel 1: odd extension  ext = [2x0 - x[512-j] | x | 2x_{L-1} - x[L-2-j]]
// ---------------------------------------------------------------------------
__global__ void build_ext_kernel(const float* __restrict__ x) {
    int idx = blockIdx.x * blockDim.x + threadIdx.x;
    if (idx >= BATCH * EXTLEN) return;
    int b = idx / EXTLEN;
    int j = idx - b * EXTLEN;
    const float* xb = x + b * SEQLEN;
    float v;
    if (j < PAD) {
        v = 2.0f * xb[0] - xb[PAD - j];
    } else if (j < PAD + SEQLEN) {
        v = xb[j - PAD];
    } else {
        int jr = j - (PAD + SEQLEN);
        v = 2.0f * xb[SEQLEN - 1] - xb[SEQLEN - 2 - jr];
    }
    g_ext[idx] = v;
}

// ---------------------------------------------------------------------------
// Kernel 2: per-band autocorrelation c[m] = sum_j b[j]*b[j+m]
// ---------------------------------------------------------------------------
__global__ void autocorr_kernel(const float* __restrict__ kern) {
    int band = blockIdx.x;
    const float* kb = kern + band * TAPS;
    __shared__ float sk[TAPS];
    __shared__ int s_last;
    int tid = threadIdx.x;
    for (int i = tid; i < TAPS; i += blockDim.x) sk[i] = kb[i];
    if (tid == 0) s_last = 0;
    __syncthreads();
    if (tid == 0) {
        int last = 0;
        for (int i = 0; i < TAPS; i++) if (sk[i] != 0.0f) last = i;
        s_last = last;
        g_M[band] = last;
    }
    __syncthreads();
    int M = s_last;
    for (int m = tid; m < TAPS; m += blockDim.x) {
        float s = 0.0f;
        if (m <= M) {
            int jmax = M - m;
            for (int j = 0; j <= jmax; j++) s = fmaf(sk[j], sk[j + m], s);
        }
        g_c[band * TAPS + m] = s;
    }
}

// ---------------------------------------------------------------------------
// Kernel 3: main correlation with packed f32x2 FMAs.
// out[b, band, i] = sum_{m=-M}^{M} c[m] * ext[b][PAD + i + m]
// CTA: one (batch, 2048-position tile); loops over bands. Thread owns 8
// consecutive outputs as 4 packed accumulators. Window kept twice in smem
// (sh, sh1 = sh shifted by 1 float) so both even- and odd-offset packed
// pairs come from aligned 128-bit loads with zero register shuffling.
// Per 4 taps: 16 FFMA2 (=32 FMA) + 2 fresh LDS.128 + 2 broadcast LDS.128.
// ---------------------------------------------------------------------------
__global__ __launch_bounds__(THREADS) void conv_kernel(float* __restrict__ out) {
    __shared__ __align__(16) float sh [SHSZ];
    __shared__ __align__(16) float sh1[SHSZ];
    __shared__ __align__(16) unsigned long long cdup[CDUPSZ];   // (c,c) pairs

    const int tid = threadIdx.x;
    const int cta = blockIdx.x;
    const int tilesPerBatch = SEQLEN / TI;          // 8
    const int tile  = cta & (tilesPerBatch - 1);
    const int batch = cta / tilesPerBatch;
    const int tileStart = tile * TI;

    // Load window ext[batch][tileStart .. tileStart + WIN) via float4
    {
        const float4* src = reinterpret_cast<const float4*>(g_ext + batch * EXTLEN + tileStart);
        float4* dst = reinterpret_cast<float4*>(sh);
        #pragma unroll
        for (int i = 0; i < WIN / 4 / THREADS; i++)          // 3 iters
            dst[tid + i * THREADS] = src[tid + i * THREADS];
        if (tid < SHSZ - WIN) sh[WIN + tid] = 0.0f;          // zero tail pad
    }
    __syncthreads();
    // Shifted shadow copy: sh1[j] = sh[j+1]
    for (int j = tid; j < SHSZ - 8; j += THREADS) sh1[j] = sh[j + 1];
    if (tid < 8) sh1[SHSZ - 8 + tid] = 0.0f;

    for (int band = 0; band < NBANDS; band++) {
        const int M  = g_M[band];
        const int Mp = (M + 3) & ~3;                // round up to mult of 4
        const int U  = 2 * Mp + 4;                  // padded tap count, mult of 4
        const int off = PAD - Mp;                   // >= 0, mult of 4
        const int n4 = U >> 2;

        __syncthreads();                            // prev band done with cdup
        // cdup[u] = packed (c[|u-Mp|], c[|u-Mp|]), zero outside [-M, M]
        const float* cb = g_c + band * TAPS;
        for (int u = tid; u < U; u += THREADS) {
            int m = u - Mp;
            int am = (m < 0) ? -m : m;
            float c = (am <= M) ? cb[am] : 0.0f;
            unsigned int bits = __float_as_uint(c);
            cdup[u] = ((unsigned long long)bits << 32) | bits;
        }
        __syncthreads();

        const int base = off + tid * POS;           // mult of 4
        const ulonglong2* w2  = reinterpret_cast<const ulonglong2*>(sh  + base);
        const ulonglong2* w2o = reinterpret_cast<const ulonglong2*>(sh1 + base);
        const ulonglong2* cd2 = reinterpret_cast<const ulonglong2*>(cdup);

        unsigned long long acc0 = 0ull, acc1 = 0ull, acc2 = 0ull, acc3 = 0ull;

        // Pipeline: A=(s0,s2) B=(s4,s6) from sh;  Ao=(s1,s3) Bo=(s5,s7) from sh1
        ulonglong2 A  = w2 [0], B  = w2 [1];
        ulonglong2 Ao = w2o[0], Bo = w2o[1];

        #pragma unroll 2
        for (int q = 0; q < n4; q++) {
            ulonglong2 C  = w2 [q + 2];             // (s8,s10) for this q
            ulonglong2 Co = w2o[q + 2];             // (s9,s11)
            ulonglong2 ca = cd2[2 * q];             // (c0c0, c1c1)
            ulonglong2 cbp = cd2[2 * q + 1];        // (c2c2, c3c3)

            // du=0 (even): pairs s0,s2,s4,s6
            ffma2(acc0, ca.x, A.x);
            ffma2(acc1, ca.x, A.y);
            ffma2(acc2, ca.x, B.x);
            ffma2(acc3, ca.x, B.y);
            // du=1 (odd): pairs s1,s3,s5,s7
            ffma2(acc0, ca.y, Ao.x);
            ffma2(acc1, ca.y, Ao.y);
            ffma2(acc2, ca.y, Bo.x);
            ffma2(acc3, ca.y, Bo.y);
            // du=2 (even): pairs s2,s4,s6,s8
            ffma2(acc0, cbp.x, A.y);
            ffma2(acc1, cbp.x, B.x);
            ffma2(acc2, cbp.x, B.y);
            ffma2(acc3, cbp.x, C.x);
            // du=3 (odd): pairs s3,s5,s7,s9
            ffma2(acc0, cbp.y, Ao.y);
            ffma2(acc1, cbp.y, Bo.x);
            ffma2(acc2, cbp.y, Bo.y);
            ffma2(acc3, cbp.y, Co.x);

            A = B; B = C; Ao = Bo; Bo = Co;
        }

        // Store 8 outputs as 4 x 64-bit words (lane0 = lower address)
        unsigned long long* op = reinterpret_cast<unsigned long long*>(
            out + ((size_t)(batch * NBANDS + band) << 14) + tileStart + tid * POS);
        op[0] = acc0; op[1] = acc1; op[2] = acc2; op[3] = acc3;
    }
}

extern "C" void kernel_launch(void* const* d_in, const int* in_sizes, int n_in,
                              void* d_out, int out_size) {
    (void)in_sizes; (void)n_in; (void)out_size;
    const float* x    = (const float*)d_in[0];
    const float* kern = (const float*)d_in[1];

    int extElems = BATCH * EXTLEN;
    build_ext_kernel<<<(extElems + 255) / 256, 256>>>(x);
    autocorr_kernel<<<NBANDS, 256>>>(kern);
    conv_kernel<<<BATCH * (SEQLEN / TI), THREADS>>>((float*)d_out);
}

// round 5
// speedup vs baseline: 5.1578x; 5.1578x over previous
#include <cuda_runtime.h>
#include <cstdint>

// ---------------- problem constants ----------------
#define BATCH    128
#define SEQLEN   16384
#define NBANDS   20
#define TAPS     513
#define PAD      512
#define EXTLEN   (SEQLEN + 2*PAD)            // 17408

// ---------------- FFT / overlap-save config ----------------
#define NFFT     4096
#define SEGSTEP  3072                        // valid outputs per segment
#define NSEG     6                           // ceil(16384/3072)
#define NPAIR    ((BATCH/2)*NSEG)            // 384 forward FFTs
#define EXTSTRIDE ((NSEG-1)*SEGSTEP + NFFT)  // 19456 (padded row)
#define NT       256

// ---------------- device scratch (static, no allocation) ----------------
__device__ float  g_ext[BATCH * EXTSTRIDE];  // odd-extended, zero-padded rows
__device__ float2 g_tw[NFFT];                // e^{-2pi i k/N}
__device__ float2 g_spec[NPAIR * NFFT];      // forward spectra
__device__ float  g_H[NBANDS * NFFT];        // real zero-phase spectra (incl. 1/N)
__device__ float  g_c[NBANDS * TAPS];        // per-band autocorrelation

// 128B smem swizzle on complex (8B) index: avoids large-stride bank conflicts
__device__ __forceinline__ int sw(int i) { return i ^ ((i >> 3) & 0xE); }

__device__ __forceinline__ float2 cmul(float2 a, float2 b) {
    return make_float2(fmaf(a.x, b.x, -a.y * b.y), fmaf(a.x, b.y, a.y * b.x));
}

// ---------------------------------------------------------------------------
// Radix-4 Stockham autosort FFT, N=4096, 256 threads, ping-pong smem buffers.
// Natural-order in, natural-order out. INV=true: conjugate twiddles (no 1/N).
// ---------------------------------------------------------------------------
template <bool INV>
__device__ float2* fft4096(float2* A, float2* B, const float2* tw, int tid) {
    float2* cur = A; float2* oth = B;
    #pragma unroll
    for (int s = 0; s < 6; s++) {
        const int twos = 2 * s;
        const int L = 1 << twos;
        __syncthreads();
        #pragma unroll
        for (int u = 0; u < 4; u++) {
            int j = u * NT + tid;               // 0..1023
            int r = j & (L - 1);
            int q = j >> twos;
            float2 a = cur[sw(j)];
            float2 b = cur[sw(j + 1024)];
            float2 c = cur[sw(j + 2048)];
            float2 d = cur[sw(j + 3072)];
            int tbase = r << (10 - twos);       // r * (1024 >> 2s)
            float2 w1 = tw[tbase];
            float2 w2 = tw[2 * tbase];
            float2 w3 = tw[3 * tbase];
            if (INV) { w1.y = -w1.y; w2.y = -w2.y; w3.y = -w3.y; }
            b = cmul(b, w1); c = cmul(c, w2); d = cmul(d, w3);
            float2 t0 = make_float2(a.x + c.x, a.y + c.y);
            float2 t1 = make_float2(a.x - c.x, a.y - c.y);
            float2 t2 = make_float2(b.x + d.x, b.y + d.y);
            float2 t3 = make_float2(b.x - d.x, b.y - d.y);
            float2 Y0 = make_float2(t0.x + t2.x, t0.y + t2.y);
            float2 Y2 = make_float2(t0.x - t2.x, t0.y - t2.y);
            float2 Y1, Y3;
            if (!INV) {      // Y1 = t1 - i t3 ; Y3 = t1 + i t3
                Y1 = make_float2(t1.x + t3.y, t1.y - t3.x);
                Y3 = make_float2(t1.x - t3.y, t1.y + t3.x);
            } else {         // conjugate butterfly
                Y1 = make_float2(t1.x - t3.y, t1.y + t3.x);
                Y3 = make_float2(t1.x + t3.y, t1.y - t3.x);
            }
            int o = (q << (twos + 2)) + r;      // q*4L + r
            oth[sw(o)]         = Y0;
            oth[sw(o + L)]     = Y1;
            oth[sw(o + 2 * L)] = Y2;
            oth[sw(o + 3 * L)] = Y3;
        }
        float2* t = cur; cur = oth; oth = t;
    }
    __syncthreads();
    return cur;
}

// ---------------------------------------------------------------------------
// setup kernels
// ---------------------------------------------------------------------------
__global__ void tw_kernel() {
    int k = blockIdx.x * blockDim.x + threadIdx.x;
    if (k < NFFT) {
        float s_, c_;
        sincospif(2.0f * (float)k / (float)NFFT, &s_, &c_);
        g_tw[k] = make_float2(c_, -s_);         // e^{-2pi i k/N}
    }
}

__global__ void build_ext_kernel(const float* __restrict__ x) {
    int idx = blockIdx.x * blockDim.x + threadIdx.x;
    if (idx >= BATCH * EXTSTRIDE) return;
    int b = idx / EXTSTRIDE;
    int j = idx - b * EXTSTRIDE;
    const float* xb = x + b * SEQLEN;
    float v;
    if (j < PAD)                    v = 2.0f * xb[0] - xb[PAD - j];
    else if (j < PAD + SEQLEN)      v = xb[j - PAD];
    else if (j < EXTLEN) {
        int jr = j - (PAD + SEQLEN);
        v = 2.0f * xb[SEQLEN - 1] - xb[SEQLEN - 2 - jr];
    } else                          v = 0.0f;   // pad tail: must be finite
    g_ext[idx] = v;
}

__global__ void autocorr_kernel(const float* __restrict__ kern) {
    int band = blockIdx.x;
    const float* kb = kern + band * TAPS;
    __shared__ float sk[TAPS];
    __shared__ int s_last;
    int tid = threadIdx.x;
    for (int i = tid; i < TAPS; i += blockDim.x) sk[i] = kb[i];
    if (tid == 0) s_last = 0;
    __syncthreads();
    if (tid == 0) {
        int last = 0;
        for (int i = 0; i < TAPS; i++) if (sk[i] != 0.0f) last = i;
        s_last = last;
    }
    __syncthreads();
    int M = s_last;
    for (int m = tid; m < TAPS; m += blockDim.x) {
        float s = 0.0f;
        if (m <= M) {
            int jmax = M - m;
            for (int j = 0; j <= jmax; j++) s = fmaf(sk[j], sk[j + m], s);
        }
        g_c[band * TAPS + m] = s;
    }
}

// H[band][f] = Re FFT(wrapped symmetric c) / N   (real zero-phase spectrum)
__global__ __launch_bounds__(NT, 2) void h_kernel() {
    extern __shared__ char smraw[];
    float2* A  = (float2*)smraw;
    float2* B  = A + NFFT;
    float2* tw = B + NFFT;
    int band = blockIdx.x, tid = threadIdx.x;
    const float* cb = g_c + band * TAPS;
    #pragma unroll
    for (int u = 0; u < NFFT / NT; u++) { int j = u * NT + tid; tw[j] = g_tw[j]; }
    #pragma unroll
    for (int u = 0; u < NFFT / NT; u++) {
        int j = u * NT + tid;
        float v = 0.0f;
        if (j <= PAD)             v = cb[j];
        else if (j >= NFFT - PAD) v = cb[NFFT - j];
        A[sw(j)] = make_float2(v, 0.0f);
    }
    float2* res = fft4096<false>(A, B, tw, tid);
    const float invn = 1.0f / (float)NFFT;
    #pragma unroll
    for (int u = 0; u < NFFT / NT; u++) {
        int j = u * NT + tid;
        g_H[band * NFFT + j] = res[sw(j)].x * invn;
    }
}

// ---------------------------------------------------------------------------
// Phase 1: forward FFT of paired segments  z = ext[2bp] + i*ext[2bp+1]
// ---------------------------------------------------------------------------
__global__ __launch_bounds__(NT, 2) void fwd_kernel() {
    extern __shared__ char smraw[];
    float2* A  = (float2*)smraw;
    float2* B  = A + NFFT;
    float2* tw = B + NFFT;
    int s = blockIdx.x, bp = blockIdx.y, tid = threadIdx.x;
    #pragma unroll
    for (int u = 0; u < NFFT / NT; u++) { int j = u * NT + tid; tw[j] = g_tw[j]; }
    const float* ea = g_ext + (size_t)(2 * bp) * EXTSTRIDE + s * SEGSTEP;
    const float* eb = ea + EXTSTRIDE;
    #pragma unroll
    for (int u = 0; u < NFFT / NT; u++) {
        int j = u * NT + tid;
        A[sw(j)] = make_float2(ea[j], eb[j]);
    }
    float2* res = fft4096<false>(A, B, tw, tid);
    float2* sp = g_spec + (size_t)(bp * NSEG + s) * NFFT;
    #pragma unroll
    for (int u = 0; u < NFFT / NT; u++) { int j = u * NT + tid; sp[j] = res[sw(j)]; }
}

// ---------------------------------------------------------------------------
// Phase 2: per (pair, band): W = H*Z, inverse FFT, write valid samples.
// Real part -> batch 2bp, imag part -> batch 2bp+1.
// ---------------------------------------------------------------------------
__global__ __launch_bounds__(NT, 2) void inv_kernel(float* __restrict__ out) {
    extern __shared__ char smraw[];
    float2* A  = (float2*)smraw;
    float2* B  = A + NFFT;
    float2* tw = B + NFFT;
    int s = blockIdx.x, bp = blockIdx.y, band = blockIdx.z, tid = threadIdx.x;
    #pragma unroll
    for (int u = 0; u < NFFT / NT; u++) { int j = u * NT + tid; tw[j] = g_tw[j]; }
    const float2* sp = g_spec + (size_t)(bp * NSEG + s) * NFFT;
    const float*  Hb = g_H + band * NFFT;
    #pragma unroll
    for (int u = 0; u < NFFT / NT; u++) {
        int j = u * NT + tid;
        float2 z = sp[j];
        float  h = Hb[j];
        A[sw(j)] = make_float2(z.x * h, z.y * h);
    }
    float2* res = fft4096<true>(A, B, tw, tid);

    size_t basea = ((size_t)(2 * bp)     * NBANDS + band) * SEQLEN;
    size_t baseb = ((size_t)(2 * bp + 1) * NBANDS + band) * SEQLEN;
    int pos0 = s * SEGSTEP;
    #pragma unroll
    for (int u = 0; u < SEGSTEP / NT; u++) {       // 12 iters
        int off = u * NT + tid;
        int pos = pos0 + off;
        if (pos < SEQLEN) {
            float2 y = res[sw(PAD + off)];
            out[basea + pos] = y.x;
            out[baseb + pos] = y.y;
        }
    }
}

// ---------------------------------------------------------------------------
extern "C" void kernel_launch(void* const* d_in, const int* in_sizes, int n_in,
                              void* d_out, int out_size) {
    (void)in_sizes; (void)n_in; (void)out_size;
    const float* x    = (const float*)d_in[0];
    const float* kern = (const float*)d_in[1];
    float* out = (float*)d_out;

    const size_t shbytes = 3 * NFFT * sizeof(float2);   // 98304
    cudaFuncSetAttribute(h_kernel,   cudaFuncAttributeMaxDynamicSharedMemorySize, (int)shbytes);
    cudaFuncSetAttribute(fwd_kernel, cudaFuncAttributeMaxDynamicSharedMemorySize, (int)shbytes);
    cudaFuncSetAttribute(inv_kernel, cudaFuncAttributeMaxDynamicSharedMemorySize, (int)shbytes);

    tw_kernel<<<(NFFT + 255) / 256, 256>>>();
    build_ext_kernel<<<(BATCH * EXTSTRIDE + 255) / 256, 256>>>(x);
    autocorr_kernel<<<NBANDS, 256>>>(kern);
    h_kernel<<<NBANDS, NT, shbytes>>>();
    fwd_kernel<<<dim3(NSEG, BATCH / 2), NT, shbytes>>>();
    inv_kernel<<<dim3(NSEG, BATCH / 2, NBANDS), NT, shbytes>>>(out);
}

// round 6
// speedup vs baseline: 8.3110x; 1.6113x over previous
#include <cuda_runtime.h>
#include <cstdint>

// ---------------- problem constants ----------------
#define BATCH    128
#define SEQLEN   16384
#define NBANDS   20
#define TAPS     513
#define PAD      512
#define EXTLEN   (SEQLEN + 2*PAD)            // 17408

// ---------------- FFT / overlap-save config ----------------
#define NFFT     4096
#define SEGSTEP  3072                        // valid outputs per segment
#define NSEG     6
#define NPAIR    ((BATCH/2)*NSEG)            // 384 forward FFTs
#define EXTSTRIDE ((NSEG-1)*SEGSTEP + NFFT)  // 19456
#define NT       256
#define NITEMS   (NBANDS*(BATCH/2)*NSEG)     // 7680 inverse items
#define PCTAS    296                         // persistent CTAs (2/SM)

// smem layout: A[4096] B[4096] T2[4096] T1[256] float2
#define SH_BYTES ((4096*3 + 256) * 8)        // 100352

// ---------------- device scratch ----------------
__device__ float  g_ext[BATCH * EXTSTRIDE];
__device__ float2 g_spec[NPAIR * NFFT];
__device__ float  g_H[NBANDS * NFFT];
__device__ float  g_c[NBANDS * TAPS];
__device__ float2 g_T1[16 * 16];             // stage-1 twiddles W^(t*r*16), [t*16+r]
__device__ float2 g_T2[16 * 256];            // stage-2 twiddles W^(t*r),    [t*256+r]

// 16-block XOR swizzle on float2 index: 2-phase (optimal 64-bit) for every
// load/store pattern of the 3 radix-16 stages.
__device__ __forceinline__ int swz(int i) { return i ^ ((i >> 4) & 15); }

__device__ __forceinline__ float2 cmul(float2 a, float2 b) {
    return make_float2(fmaf(a.x, b.x, -a.y * b.y), fmaf(a.x, b.y, a.y * b.x));
}
template <bool INV>
__device__ __forceinline__ float2 cmulc(float2 a, float cx, float cy) {
    if (INV) cy = -cy;
    return make_float2(fmaf(a.x, cx, -a.y * cy), fmaf(a.x, cy, a.y * cx));
}

// in-place DFT4: inputs order n=0..3 in (x0..x3); outputs k=0..3 same slots
template <bool INV>
__device__ __forceinline__ void dft4(float2& x0, float2& x1, float2& x2, float2& x3) {
    float2 t0 = make_float2(x0.x + x2.x, x0.y + x2.y);
    float2 t1 = make_float2(x0.x - x2.x, x0.y - x2.y);
    float2 t2 = make_float2(x1.x + x3.x, x1.y + x3.y);
    float2 t3 = make_float2(x1.x - x3.x, x1.y - x3.y);
    x0 = make_float2(t0.x + t2.x, t0.y + t2.y);
    x2 = make_float2(t0.x - t2.x, t0.y - t2.y);
    if (!INV) {
        x1 = make_float2(t1.x + t3.y, t1.y - t3.x);   // t1 - i t3
        x3 = make_float2(t1.x - t3.y, t1.y + t3.x);   // t1 + i t3
    } else {
        x1 = make_float2(t1.x - t3.y, t1.y + t3.x);
        x3 = make_float2(t1.x + t3.y, t1.y - t3.x);
    }
}

// W16^m constants (forward): cos(pi m/8), -sin(pi m/8)
#define W1X  0.92387953251128674f
#define W1Y -0.38268343236508978f
#define W2X  0.70710678118654752f
#define W2Y -0.70710678118654752f
#define W3X  0.38268343236508978f
#define W3Y -0.92387953251128674f
#define W6X -0.70710678118654752f
#define W6Y -0.70710678118654752f
#define W9X -0.92387953251128674f
#define W9Y  0.38268343236508978f

// DFT16 in registers. Input a[n], n=0..15. Output y[t] = a[4*(t&3) + (t>>2)].
template <bool INV>
__device__ __forceinline__ void dft16(float2* a) {
    // pass 1: DFT4 over n1 (n = 4n1+n0); result c[n0][k0] at a[n0+4k0]
    #pragma unroll
    for (int n0 = 0; n0 < 4; n0++)
        dft4<INV>(a[n0], a[n0 + 4], a[n0 + 8], a[n0 + 12]);
    // twiddles W16^{n0*k0}
    a[5]  = cmulc<INV>(a[5],  W1X, W1Y);   // n0=1,k0=1
    a[9]  = cmulc<INV>(a[9],  W2X, W2Y);   // n0=1,k0=2
    a[13] = cmulc<INV>(a[13], W3X, W3Y);   // n0=1,k0=3
    a[6]  = cmulc<INV>(a[6],  W2X, W2Y);   // n0=2,k0=1
    // n0=2,k0=2: W16^4 = -i (fwd) / +i (inv)
    a[10] = INV ? make_float2(-a[10].y, a[10].x) : make_float2(a[10].y, -a[10].x);
    a[14] = cmulc<INV>(a[14], W6X, W6Y);   // n0=2,k0=3
    a[7]  = cmulc<INV>(a[7],  W3X, W3Y);   // n0=3,k0=1
    a[11] = cmulc<INV>(a[11], W6X, W6Y);   // n0=3,k0=2
    a[15] = cmulc<INV>(a[15], W9X, W9Y);   // n0=3,k0=3
    // pass 2: DFT4 over n0 for each k0; X[k0+4k1] lands at a[4k0+k1]
    #pragma unroll
    for (int k0 = 0; k0 < 4; k0++)
        dft4<INV>(a[4 * k0], a[4 * k0 + 1], a[4 * k0 + 2], a[4 * k0 + 3]);
}
#define PERM(t) ((((t) & 3) << 2) | ((t) >> 2))

// ---------------------------------------------------------------------------
// radix-16 Stockham FFT-4096, 3 stages, 256 threads. Input in A (swizzled),
// result returned (= B, swizzled). Natural order in/out.
// ---------------------------------------------------------------------------
template <bool INV>
__device__ float2* fft_r16(float2* A, float2* B, const float2* T1,
                           const float2* T2, int tid) {
    float2 a[16];
    // ---- stage 0: L=1 (twiddles trivial), A -> B
    __syncthreads();
    #pragma unroll
    for (int t = 0; t < 16; t++) a[t] = A[swz(tid + t * 256)];
    dft16<INV>(a);
    #pragma unroll
    for (int t = 0; t < 16; t++) B[swz(tid * 16 + t)] = a[PERM(t)];
    // ---- stage 1: L=16, B -> A
    __syncthreads();
    #pragma unroll
    for (int t = 0; t < 16; t++) a[t] = B[swz(tid + t * 256)];
    {
        int r = tid & 15;
        #pragma unroll
        for (int t = 1; t < 16; t++) {
            float2 w = T1[t * 16 + r];
            if (INV) w.y = -w.y;
            a[t] = cmul(a[t], w);
        }
    }
    dft16<INV>(a);
    {
        int o = (tid >> 4) * 256 + (tid & 15);
        #pragma unroll
        for (int t = 0; t < 16; t++) A[swz(o + t * 16)] = a[PERM(t)];
    }
    // ---- stage 2: L=256, A -> B
    __syncthreads();
    #pragma unroll
    for (int t = 0; t < 16; t++) a[t] = A[swz(tid + t * 256)];
    #pragma unroll
    for (int t = 1; t < 16; t++) {
        float2 w = T2[t * 256 + tid];
        if (INV) w.y = -w.y;
        a[t] = cmul(a[t], w);
    }
    dft16<INV>(a);
    #pragma unroll
    for (int t = 0; t < 16; t++) B[swz(tid + t * 256)] = a[PERM(t)];
    __syncthreads();
    return B;
}

__device__ __forceinline__ void load_tables(float2* T1, float2* T2, int tid) {
    #pragma unroll
    for (int u = 0; u < 16; u++) T2[u * 256 + tid] = g_T2[u * 256 + tid];
    T1[tid & 255] = g_T1[tid & 255];
}

// ---------------------------------------------------------------------------
// setup kernels
// ---------------------------------------------------------------------------
__global__ void setup_kernel() {
    int i = blockIdx.x * blockDim.x + threadIdx.x;
    if (i < 16 * 256) {
        int t = i >> 8, r = i & 255;
        float s_, c_;
        sincospif(2.0f * (float)(t * r) / (float)NFFT, &s_, &c_);
        g_T2[i] = make_float2(c_, -s_);
    }
    if (i < 256) {
        int t = i >> 4, r = i & 15;
        float s_, c_;
        sincospif(2.0f * (float)(t * r * 16) / (float)NFFT, &s_, &c_);
        g_T1[i] = make_float2(c_, -s_);
    }
}

__global__ void build_ext_kernel(const float* __restrict__ x) {
    int idx = blockIdx.x * blockDim.x + threadIdx.x;
    if (idx >= BATCH * EXTSTRIDE) return;
    int b = idx / EXTSTRIDE;
    int j = idx - b * EXTSTRIDE;
    const float* xb = x + b * SEQLEN;
    float v;
    if (j < PAD)               v = 2.0f * xb[0] - xb[PAD - j];
    else if (j < PAD + SEQLEN) v = xb[j - PAD];
    else if (j < EXTLEN) {
        int jr = j - (PAD + SEQLEN);
        v = 2.0f * xb[SEQLEN - 1] - xb[SEQLEN - 2 - jr];
    } else                     v = 0.0f;
    g_ext[idx] = v;
}

__global__ void autocorr_kernel(const float* __restrict__ kern) {
    int band = blockIdx.x;
    const float* kb = kern + band * TAPS;
    __shared__ float sk[TAPS];
    __shared__ int s_last;
    int tid = threadIdx.x;
    for (int i = tid; i < TAPS; i += blockDim.x) sk[i] = kb[i];
    if (tid == 0) s_last = 0;
    __syncthreads();
    if (tid == 0) {
        int last = 0;
        for (int i = 0; i < TAPS; i++) if (sk[i] != 0.0f) last = i;
        s_last = last;
    }
    __syncthreads();
    int M = s_last;
    for (int m = tid; m < TAPS; m += blockDim.x) {
        float s = 0.0f;
        if (m <= M) {
            int jmax = M - m;
            for (int j = 0; j <= jmax; j++) s = fmaf(sk[j], sk[j + m], s);
        }
        g_c[band * TAPS + m] = s;
    }
}

// H[band][f] = Re FFT(wrapped symmetric autocorr) / N
__global__ __launch_bounds__(NT, 2) void h_kernel() {
    extern __shared__ float2 sm[];
    float2* A = sm; float2* B = sm + 4096; float2* T2 = sm + 8192; float2* T1 = sm + 12288;
    int band = blockIdx.x, tid = threadIdx.x;
    load_tables(T1, T2, tid);
    const float* cb = g_c + band * TAPS;
    #pragma unroll
    for (int u = 0; u < 16; u++) {
        int j = u * 256 + tid;
        float v = 0.0f;
        if (j <= PAD)             v = cb[j];
        else if (j >= NFFT - PAD) v = cb[NFFT - j];
        A[swz(j)] = make_float2(v, 0.0f);
    }
    float2* res = fft_r16<false>(A, B, T1, T2, tid);
    const float invn = 1.0f / (float)NFFT;
    #pragma unroll
    for (int u = 0; u < 16; u++) {
        int j = u * 256 + tid;
        g_H[band * NFFT + j] = res[swz(j)].x * invn;
    }
}

// forward: z = ext[2bp] + i*ext[2bp+1], one segment per CTA
__global__ __launch_bounds__(NT, 2) void fwd_kernel() {
    extern __shared__ float2 sm[];
    float2* A = sm; float2* B = sm + 4096; float2* T2 = sm + 8192; float2* T1 = sm + 12288;
    int s = blockIdx.x, bp = blockIdx.y, tid = threadIdx.x;
    load_tables(T1, T2, tid);
    const float* ea = g_ext + (size_t)(2 * bp) * EXTSTRIDE + s * SEGSTEP;
    const float* eb = ea + EXTSTRIDE;
    #pragma unroll
    for (int u = 0; u < 16; u++) {
        int j = u * 256 + tid;
        A[swz(j)] = make_float2(ea[j], eb[j]);
    }
    float2* res = fft_r16<false>(A, B, T1, T2, tid);
    float2* sp = g_spec + (size_t)(bp * NSEG + s) * NFFT;
    #pragma unroll
    for (int u = 0; u < 16; u++) { int j = u * 256 + tid; sp[j] = res[swz(j)]; }
}

// inverse: persistent CTAs, tables loaded once; loop over (band, bp, s) items
__global__ __launch_bounds__(NT, 2) void inv_kernel(float* __restrict__ out) {
    extern __shared__ float2 sm[];
    float2* A = sm; float2* B = sm + 4096; float2* T2 = sm + 8192; float2* T1 = sm + 12288;
    int tid = threadIdx.x;
    load_tables(T1, T2, tid);
    for (int item = blockIdx.x; item < NITEMS; item += PCTAS) {
        int band = item / (NSEG * (BATCH / 2));
        int rem  = item - band * NSEG * (BATCH / 2);
        int bp   = rem / NSEG;
        int s    = rem - bp * NSEG;
        const float2* sp = g_spec + (size_t)(bp * NSEG + s) * NFFT;
        const float*  Hb = g_H + band * NFFT;
        #pragma unroll
        for (int u = 0; u < 16; u++) {
            int j = u * 256 + tid;
            float2 z = sp[j];
            float  h = Hb[j];
            A[swz(j)] = make_float2(z.x * h, z.y * h);
        }
        float2* res = fft_r16<true>(A, B, T1, T2, tid);
        size_t basea = ((size_t)(2 * bp) * NBANDS + band) * SEQLEN;
        size_t baseb = basea + (size_t)NBANDS * SEQLEN;
        int pos0 = s * SEGSTEP;
        #pragma unroll
        for (int u = 0; u < SEGSTEP / NT; u++) {
            int off = u * 256 + tid;
            int pos = pos0 + off;
            if (pos < SEQLEN) {
                float2 y = res[swz(PAD + off)];
                out[basea + pos] = y.x;
                out[baseb + pos] = y.y;
            }
        }
        __syncthreads();   // B fully consumed before next item's stage-0 writes
    }
}

// ---------------------------------------------------------------------------
extern "C" void kernel_launch(void* const* d_in, const int* in_sizes, int n_in,
                              void* d_out, int out_size) {
    (void)in_sizes; (void)n_in; (void)out_size;
    const float* x    = (const float*)d_in[0];
    const float* kern = (const float*)d_in[1];
    float* out = (float*)d_out;

    cudaFuncSetAttribute(h_kernel,   cudaFuncAttributeMaxDynamicSharedMemorySize, SH_BYTES);
    cudaFuncSetAttribute(fwd_kernel, cudaFuncAttributeMaxDynamicSharedMemorySize, SH_BYTES);
    cudaFuncSetAttribute(inv_kernel, cudaFuncAttributeMaxDynamicSharedMemorySize, SH_BYTES);

    setup_kernel<<<16, 256>>>();
    build_ext_kernel<<<(BATCH * EXTSTRIDE + 255) / 256, 256>>>(x);
    autocorr_kernel<<<NBANDS, 256>>>(kern);
    h_kernel<<<NBANDS, NT, SH_BYTES>>>();
    fwd_kernel<<<dim3(NSEG, BATCH / 2), NT, SH_BYTES>>>();
    inv_kernel<<<PCTAS, NT, SH_BYTES>>>(out);
}

// round 8
// speedup vs baseline: 10.0366x; 1.2076x over previous
#include <cuda_runtime.h>
#include <cstdint>

// ---------------- problem constants ----------------
#define BATCH    128
#define SEQLEN   16384
#define NBANDS   20
#define TAPS     513
#define PAD      512
#define EXTLEN   (SEQLEN + 2*PAD)            // 17408

// ---------------- FFT / overlap-save config ----------------
#define NFFT     4096
#define SEGSTEP  3072                        // valid outputs per segment
#define NSEG     6
#define NPAIR    ((BATCH/2)*NSEG)            // 384 forward FFTs
#define EXTSTRIDE ((NSEG-1)*SEGSTEP + NFFT)  // 19456
#define NT       256
#define NITEMS   (NBANDS*(BATCH/2)*NSEG)     // 7680 inverse items
#define PCTAS    (148*3)                     // persistent CTAs (3/SM)

// smem: A[4096] B[4096] T1[256] Ta[256] float2
#define SH_BYTES ((4096*2 + 512) * 8)        // 69632

// ---------------- device scratch ----------------
__device__ float  g_ext[BATCH * EXTSTRIDE];
__device__ float2 g_spec[NPAIR * NFFT];
__device__ float  g_H[NBANDS * NFFT];
__device__ float  g_c[NBANDS * TAPS];
__device__ float2 g_T1[256];                 // W_4096^(16*t*r), [t*16+r]
__device__ float2 g_Ta[256];                 // W_4096^(t*r),    [t*16+r]

// 16-block XOR swizzle on float2 index (2-phase for all stage patterns)
__device__ __forceinline__ int swz(int i) { return i ^ ((i >> 4) & 15); }

__device__ __forceinline__ float2 cmul(float2 a, float2 b) {
    return make_float2(fmaf(a.x, b.x, -a.y * b.y), fmaf(a.x, b.y, a.y * b.x));
}
template <bool INV>
__device__ __forceinline__ float2 cmulc(float2 a, float cx, float cy) {
    if (INV) cy = -cy;
    return make_float2(fmaf(a.x, cx, -a.y * cy), fmaf(a.x, cy, a.y * cx));
}

template <bool INV>
__device__ __forceinline__ void dft4(float2& x0, float2& x1, float2& x2, float2& x3) {
    float2 t0 = make_float2(x0.x + x2.x, x0.y + x2.y);
    float2 t1 = make_float2(x0.x - x2.x, x0.y - x2.y);
    float2 t2 = make_float2(x1.x + x3.x, x1.y + x3.y);
    float2 t3 = make_float2(x1.x - x3.x, x1.y - x3.y);
    x0 = make_float2(t0.x + t2.x, t0.y + t2.y);
    x2 = make_float2(t0.x - t2.x, t0.y - t2.y);
    if (!INV) {
        x1 = make_float2(t1.x + t3.y, t1.y - t3.x);
        x3 = make_float2(t1.x - t3.y, t1.y + t3.x);
    } else {
        x1 = make_float2(t1.x - t3.y, t1.y + t3.x);
        x3 = make_float2(t1.x + t3.y, t1.y - t3.x);
    }
}

#define W1X  0.92387953251128674f
#define W1Y -0.38268343236508978f
#define W2X  0.70710678118654752f
#define W2Y -0.70710678118654752f
#define W3X  0.38268343236508978f
#define W3Y -0.92387953251128674f
#define W6X -0.70710678118654752f
#define W6Y -0.70710678118654752f
#define W9X -0.92387953251128674f
#define W9Y  0.38268343236508978f

template <bool INV>
__device__ __forceinline__ void dft16(float2* a) {
    #pragma unroll
    for (int n0 = 0; n0 < 4; n0++)
        dft4<INV>(a[n0], a[n0 + 4], a[n0 + 8], a[n0 + 12]);
    a[5]  = cmulc<INV>(a[5],  W1X, W1Y);
    a[9]  = cmulc<INV>(a[9],  W2X, W2Y);
    a[13] = cmulc<INV>(a[13], W3X, W3Y);
    a[6]  = cmulc<INV>(a[6],  W2X, W2Y);
    a[10] = INV ? make_float2(-a[10].y, a[10].x) : make_float2(a[10].y, -a[10].x);
    a[14] = cmulc<INV>(a[14], W6X, W6Y);
    a[7]  = cmulc<INV>(a[7],  W3X, W3Y);
    a[11] = cmulc<INV>(a[11], W6X, W6Y);
    a[15] = cmulc<INV>(a[15], W9X, W9Y);
    #pragma unroll
    for (int k0 = 0; k0 < 4; k0++)
        dft4<INV>(a[4 * k0], a[4 * k0 + 1], a[4 * k0 + 2], a[4 * k0 + 3]);
}
#define PERM(t) ((((t) & 3) << 2) | ((t) >> 2))

// ---------------------------------------------------------------------------
// Core FFT-4096: input a[t] = x[tid + t*256] in registers; output (natural
// order) x[tid + t*256] = a[PERM(t)] in registers. 2 smem round-trips.
// ---------------------------------------------------------------------------
template <bool INV>
__device__ __forceinline__ void fft_mid(float2* a, float2* X, float2* Y,
                                        const float2* T1, const float2* Ta, int tid) {
    const int rlo = tid & 15, rhi = tid >> 4;
    // stage 0 (L=1)
    dft16<INV>(a);
    #pragma unroll
    for (int t = 0; t < 16; t++) X[swz(tid * 16 + t)] = a[PERM(t)];
    __syncthreads();
    // stage 1 (L=16)
    #pragma unroll
    for (int t = 0; t < 16; t++) a[t] = X[swz(tid + t * 256)];
    #pragma unroll
    for (int t = 1; t < 16; t++) {
        float2 w = T1[t * 16 + rlo];
        if (INV) w.y = -w.y;
        a[t] = cmul(a[t], w);
    }
    dft16<INV>(a);
    {
        int o = rhi * 256 + rlo;
        #pragma unroll
        for (int t = 0; t < 16; t++) Y[swz(o + t * 16)] = a[PERM(t)];
    }
    __syncthreads();
    // stage 2 (L=256), twiddle W^(t*tid) = Ta[t,rlo] * T1[t,rhi]
    #pragma unroll
    for (int t = 0; t < 16; t++) a[t] = Y[swz(tid + t * 256)];
    #pragma unroll
    for (int t = 1; t < 16; t++) {
        float2 wa = Ta[t * 16 + rlo];
        float2 wb = T1[t * 16 + rhi];
        if (INV) { wa.y = -wa.y; wb.y = -wb.y; }
        a[t] = cmul(a[t], cmul(wa, wb));
    }
    dft16<INV>(a);
}

__device__ __forceinline__ void load_tables(float2* T1, float2* Ta, int tid) {
    T1[tid] = g_T1[tid];
    Ta[tid] = g_Ta[tid];
}

// ---------------------------------------------------------------------------
// setup kernels
// ---------------------------------------------------------------------------
__global__ void setup_kernel() {
    int i = threadIdx.x;              // 0..255
    int t = i >> 4, r = i & 15;
    float s_, c_;
    sincospif(2.0f * (float)(16 * t * r) / (float)NFFT, &s_, &c_);
    g_T1[i] = make_float2(c_, -s_);
    sincospif(2.0f * (float)(t * r) / (float)NFFT, &s_, &c_);
    g_Ta[i] = make_float2(c_, -s_);
}

__global__ void build_ext_kernel(const float* __restrict__ x) {
    int idx = blockIdx.x * blockDim.x + threadIdx.x;
    if (idx >= BATCH * EXTSTRIDE) return;
    int b = idx / EXTSTRIDE;
    int j = idx - b * EXTSTRIDE;
    const float* xb = x + b * SEQLEN;
    float v;
    if (j < PAD)               v = 2.0f * xb[0] - xb[PAD - j];
    else if (j < PAD + SEQLEN) v = xb[j - PAD];
    else if (j < EXTLEN) {
        int jr = j - (PAD + SEQLEN);
        v = 2.0f * xb[SEQLEN - 1] - xb[SEQLEN - 2 - jr];
    } else                     v = 0.0f;
    g_ext[idx] = v;
}

__global__ void autocorr_kernel(const float* __restrict__ kern) {
    int band = blockIdx.x;
    const float* kb = kern + band * TAPS;
    __shared__ float sk[TAPS];
    __shared__ int s_last;
    int tid = threadIdx.x;
    for (int i = tid; i < TAPS; i += blockDim.x) sk[i] = kb[i];
    if (tid == 0) s_last = 0;
    __syncthreads();
    if (tid == 0) {
        int last = 0;
        for (int i = 0; i < TAPS; i++) if (sk[i] != 0.0f) last = i;
        s_last = last;
    }
    __syncthreads();
    int M = s_last;
    for (int m = tid; m < TAPS; m += blockDim.x) {
        float s = 0.0f;
        if (m <= M) {
            int jmax = M - m;
            for (int j = 0; j <= jmax; j++) s = fmaf(sk[j], sk[j + m], s);
        }
        g_c[band * TAPS + m] = s;
    }
}

// H[band][f] = Re FFT(wrapped symmetric autocorr) / N
__global__ __launch_bounds__(NT, 3) void h_kernel() {
    extern __shared__ float2 sm[];
    float2* A = sm; float2* B = sm + 4096; float2* T1 = sm + 8192; float2* Ta = sm + 8448;
    int band = blockIdx.x, tid = threadIdx.x;
    load_tables(T1, Ta, tid);
    __syncthreads();
    const float* cb = g_c + band * TAPS;
    float2 a[16];
    #pragma unroll
    for (int t = 0; t < 16; t++) {
        int j = tid + t * 256;
        float v = 0.0f;
        if (j <= PAD)             v = cb[j];
        else if (j >= NFFT - PAD) v = cb[NFFT - j];
        a[t] = make_float2(v, 0.0f);
    }
    fft_mid<false>(a, A, B, T1, Ta, tid);
    const float invn = 1.0f / (float)NFFT;
    #pragma unroll
    for (int t = 0; t < 16; t++)
        g_H[band * NFFT + tid + t * 256] = a[PERM(t)].x * invn;
}

// forward: z = ext[2bp] + i*ext[2bp+1], one segment per CTA
__global__ __launch_bounds__(NT, 3) void fwd_kernel() {
    extern __shared__ float2 sm[];
    float2* A = sm; float2* B = sm + 4096; float2* T1 = sm + 8192; float2* Ta = sm + 8448;
    int s = blockIdx.x, bp = blockIdx.y, tid = threadIdx.x;
    load_tables(T1, Ta, tid);
    __syncthreads();
    const float* ea = g_ext + (size_t)(2 * bp) * EXTSTRIDE + s * SEGSTEP;
    const float* eb = ea + EXTSTRIDE;
    float2 a[16];
    #pragma unroll
    for (int t = 0; t < 16; t++) {
        int j = tid + t * 256;
        a[t] = make_float2(ea[j], eb[j]);
    }
    fft_mid<false>(a, A, B, T1, Ta, tid);
    float2* sp = g_spec + (size_t)(bp * NSEG + s) * NFFT;
    #pragma unroll
    for (int t = 0; t < 16; t++)
        sp[tid + t * 256] = a[PERM(t)];
}

// inverse: persistent CTAs; gmem->reg input, reg->gmem output
__global__ __launch_bounds__(NT, 3) void inv_kernel(float* __restrict__ out) {
    extern __shared__ float2 sm[];
    float2* A = sm; float2* B = sm + 4096; float2* T1 = sm + 8192; float2* Ta = sm + 8448;
    int tid = threadIdx.x;
    load_tables(T1, Ta, tid);
    __syncthreads();
    for (int item = blockIdx.x; item < NITEMS; item += PCTAS) {
        int band = item / (NSEG * (BATCH / 2));
        int rem  = item - band * NSEG * (BATCH / 2);
        int bp   = rem / NSEG;
        int s    = rem - bp * NSEG;
        const float2* sp = g_spec + (size_t)(bp * NSEG + s) * NFFT;
        const float*  Hb = g_H + band * NFFT;
        float2 a[16];
        #pragma unroll
        for (int t = 0; t < 16; t++) {
            int j = tid + t * 256;
            float2 z = sp[j];
            float  h = Hb[j];
            a[t] = make_float2(z.x * h, z.y * h);
        }
        fft_mid<true>(a, A, B, T1, Ta, tid);
        // direct register -> gmem output: j = tid + t*256, valid t = 2..13
        size_t basea = ((size_t)(2 * bp) * NBANDS + band) * SEQLEN;
        size_t baseb = basea + (size_t)NBANDS * SEQLEN;
        int pos0 = s * SEGSTEP - PAD + tid;
        #pragma unroll
        for (int t = 2; t <= 13; t++) {
            int pos = pos0 + t * 256;
            if (pos < SEQLEN) {
                float2 y = a[PERM(t)];
                out[basea + pos] = y.x;
                out[baseb + pos] = y.y;
            }
        }
        // no trailing sync needed: next item's first barrier orders reuse
    }
}

// ---------------------------------------------------------------------------
extern "C" void kernel_launch(void* const* d_in, const int* in_sizes, int n_in,
                              void* d_out, int out_size) {
    (void)in_sizes; (void)n_in; (void)out_size;
    const float* x    = (const float*)d_in[0];
    const float* kern = (const float*)d_in[1];
    float* out = (float*)d_out;

    cudaFuncSetAttribute(h_kernel,   cudaFuncAttributeMaxDynamicSharedMemorySize, SH_BYTES);
    cudaFuncSetAttribute(fwd_kernel, cudaFuncAttributeMaxDynamicSharedMemorySize, SH_BYTES);
    cudaFuncSetAttribute(inv_kernel, cudaFuncAttributeMaxDynamicSharedMemorySize, SH_BYTES);

    setup_kernel<<<1, 256>>>();
    build_ext_kernel<<<(BATCH * EXTSTRIDE + 255) / 256, 256>>>(x);
    autocorr_kernel<<<NBANDS, 256>>>(kern);
    h_kernel<<<NBANDS, NT, SH_BYTES>>>();
    fwd_kernel<<<dim3(NSEG, BATCH / 2), NT, SH_BYTES>>>();
    inv_kernel<<<PCTAS, NT, SH_BYTES>>>(out);
}